// round 8
// baseline (speedup 1.0000x reference)
#include <cuda_runtime.h>

// Problem constants (fixed shapes from reference_code)
#define KK    21
#define HH    512
#define WW    512
#define HO    492
#define WO    492
#define CC    10
#define CTR   220          // C*K + C
#define NTAP  440          // K*K - 1
#define NTG   8            // tap groups per row
#define TPG   55           // taps per group (440/8)
#define X4N   123          // float4 tiles per output row (492/4)
#define PLANE ((size_t)HO * (size_t)WO)   // 242064 elements per tap channel

#define SMOOTH_BLOCKS (HO * NTG)   // 3936
#define FID_BLOCKS    256          // 65536 float4s / 256 threads

// Deterministic per-block partials (overwritten fully on every launch).
__device__ double g_smooth_part[SMOOTH_BLOCKS];
__device__ double g_fid_part[FID_BLOCKS];

__device__ __forceinline__ float warp_reduce(float v) {
#pragma unroll
    for (int o = 16; o > 0; o >>= 1)
        v += __shfl_down_sync(0xffffffffu, v, o);
    return v;
}

// One block = one (output row y, tap group g). 128 threads; thread i owns
// 4 consecutive x positions. w_ij read once (HBM-bound pass); output rows
// hit L1/L2 (1 MB array, heavy reuse).
__global__ __launch_bounds__(128) void smooth_kernel(
    const float* __restrict__ outp,
    const float* __restrict__ w,
    const float* __restrict__ bias)
{
    const int b   = blockIdx.x;
    const int y   = b >> 3;      // / NTG
    const int g   = b & 7;       // % NTG
    const int tid = threadIdx.x;

    __shared__ float sbias[TPG];
    if (tid < TPG) sbias[tid] = bias[g * TPG + tid];
    __syncthreads();

    float acc = 0.0f;

    if (tid < X4N) {
        const int xb = tid << 2;  // x base (0..488)

        // Center taps: out[y+C, xb+C .. xb+C+3] (unaligned -> 4 scalars, L1 hits)
        const float* crow = outp + (size_t)(y + CC) * WW + xb + CC;
        const float c0 = crow[0];
        const float c1 = crow[1];
        const float c2 = crow[2];
        const float c3 = crow[3];

        const float* wbase = w + (size_t)(g * TPG) * PLANE + (size_t)y * WO + xb;

#pragma unroll 5
        for (int i = 0; i < TPG; ++i) {
            const int t   = g * TPG + i;
            const int raw = t + (t >= CTR ? 1 : 0);   // skip deleted center channel
            const int dy  = raw / KK;
            const int dx  = raw - dy * KK;

            const float4 wv = *reinterpret_cast<const float4*>(wbase + (size_t)i * PLANE);

            const float* nrow = outp + (size_t)(y + dy) * WW + xb + dx;
            const float bt = sbias[i];

            const float d0 = (c0 - nrow[0]) + bt;
            const float d1 = (c1 - nrow[1]) + bt;
            const float d2 = (c2 - nrow[2]) + bt;
            const float d3 = (c3 - nrow[3]) + bt;

            acc = fmaf(wv.x * d0, d0, acc);
            acc = fmaf(wv.y * d1, d1, acc);
            acc = fmaf(wv.z * d2, d2, acc);
            acc = fmaf(wv.w * d3, d3, acc);
        }
    }

    // Block reduction (4 warps)
    __shared__ float swarp[4];
    const float wsum = warp_reduce(acc);
    if ((tid & 31) == 0) swarp[tid >> 5] = wsum;
    __syncthreads();
    if (tid == 0) {
        g_smooth_part[b] = (double)(swarp[0] + swarp[1] + swarp[2] + swarp[3]);
    }
}

// Fidelity: sum (output - target)^2 over 512*512 elements.
// 256 blocks x 256 threads, one float4 per thread (65536 float4s exactly).
__global__ __launch_bounds__(256) void fid_kernel(
    const float* __restrict__ outp,
    const float* __restrict__ targ)
{
    const int idx = blockIdx.x * 256 + threadIdx.x;
    const float4 o = reinterpret_cast<const float4*>(outp)[idx];
    const float4 t = reinterpret_cast<const float4*>(targ)[idx];
    const float e0 = o.x - t.x;
    const float e1 = o.y - t.y;
    const float e2 = o.z - t.z;
    const float e3 = o.w - t.w;
    float acc = e0 * e0 + e1 * e1 + e2 * e2 + e3 * e3;

    __shared__ float swarp[8];
    acc = warp_reduce(acc);
    if ((threadIdx.x & 31) == 0) swarp[threadIdx.x >> 5] = acc;
    __syncthreads();
    if (threadIdx.x == 0) {
        float s = 0.0f;
#pragma unroll
        for (int i = 0; i < 8; ++i) s += swarp[i];
        g_fid_part[blockIdx.x] = (double)s;
    }
}

// Single-block final reduction over partials; writes the scalar result.
__global__ __launch_bounds__(256) void finalize_kernel(float* __restrict__ out)
{
    double s = 0.0, f = 0.0;
    for (int i = threadIdx.x; i < SMOOTH_BLOCKS; i += 256) s += g_smooth_part[i];
    for (int i = threadIdx.x; i < FID_BLOCKS; i += 256)    f += g_fid_part[i];

    __shared__ double ss[256];
    __shared__ double sf[256];
    ss[threadIdx.x] = s;
    sf[threadIdx.x] = f;
    __syncthreads();
#pragma unroll
    for (int stride = 128; stride > 0; stride >>= 1) {
        if (threadIdx.x < stride) {
            ss[threadIdx.x] += ss[threadIdx.x + stride];
            sf[threadIdx.x] += sf[threadIdx.x + stride];
        }
        __syncthreads();
    }
    if (threadIdx.x == 0) {
        // smooth = H*W*LAM * mean(w*d*d);  fidelity = mean((o-t)^2)
        const double n_smooth = (double)NTAP * (double)HO * (double)WO;
        const double smooth = (double)HH * (double)WW * 128.0 * (ss[0] / n_smooth);
        const double fid    = sf[0] / ((double)HH * (double)WW);
        out[0] = (float)(smooth + fid);
    }
}

extern "C" void kernel_launch(void* const* d_in, const int* in_sizes, int n_in,
                              void* d_out, int out_size)
{
    const float* outp = (const float*)d_in[0];   // output (H, W)
    const float* targ = (const float*)d_in[1];   // target (H, W)
    const float* wij  = (const float*)d_in[2];   // w_ij (440, 492, 492)
    const float* bias = (const float*)d_in[3];   // bias (440,)
    float* out = (float*)d_out;

    smooth_kernel<<<SMOOTH_BLOCKS, 128>>>(outp, wij, bias);
    fid_kernel<<<FID_BLOCKS, 256>>>(outp, targ);
    finalize_kernel<<<1, 256>>>(out);
}

// round 9
// speedup vs baseline: 1.0651x; 1.0651x over previous
#include <cuda_runtime.h>

// Problem constants (fixed shapes from reference_code)
#define KK    21
#define HH    512
#define WW    512
#define HO    492
#define WO    492
#define CC    10
#define CTR   220          // C*K + C
#define NTAP  440          // K*K - 1
#define NTG   8            // tap groups per row
#define TPG   55           // taps per group (440/8)
#define X4N   123          // float4 tiles per output row (492/4)
#define PLANE ((size_t)HO * (size_t)WO)   // 242064 elements per tap channel

#define SMOOTH_BLOCKS (HO * NTG)   // 3936
#define FID_BLOCKS    256          // 65536 float4s / 256 threads

// Deterministic per-block partials (overwritten fully on every launch).
__device__ double g_smooth_part[SMOOTH_BLOCKS];
__device__ double g_fid_part[FID_BLOCKS];

__device__ __forceinline__ float warp_reduce(float v) {
#pragma unroll
    for (int o = 16; o > 0; o >>= 1)
        v += __shfl_down_sync(0xffffffffu, v, o);
    return v;
}

// One block = one (output row y, tap group g). 128 threads; thread i owns
// 4 consecutive x positions. w_ij read once (HBM-bound pass); output rows
// hit L1/L2 (1 MB array, heavy reuse).
__global__ __launch_bounds__(128) void smooth_kernel(
    const float* __restrict__ outp,
    const float* __restrict__ w,
    const float* __restrict__ bias)
{
    const int b   = blockIdx.x;
    const int y   = b >> 3;      // / NTG
    const int g   = b & 7;       // % NTG
    const int tid = threadIdx.x;

    __shared__ float sbias[TPG];
    if (tid < TPG) sbias[tid] = bias[g * TPG + tid];
    __syncthreads();

    float acc = 0.0f;

    if (tid < X4N) {
        const int xb = tid << 2;  // x base (0..488)

        // Center taps: out[y+C, xb+C .. xb+C+3] (unaligned -> 4 scalars, L1 hits)
        const float* crow = outp + (size_t)(y + CC) * WW + xb + CC;
        const float c0 = crow[0];
        const float c1 = crow[1];
        const float c2 = crow[2];
        const float c3 = crow[3];

        const float* wbase = w + (size_t)(g * TPG) * PLANE + (size_t)y * WO + xb;

#pragma unroll 5
        for (int i = 0; i < TPG; ++i) {
            const int t   = g * TPG + i;
            const int raw = t + (t >= CTR ? 1 : 0);   // skip deleted center channel
            const int dy  = raw / KK;
            const int dx  = raw - dy * KK;

            const float4 wv = *reinterpret_cast<const float4*>(wbase + (size_t)i * PLANE);

            const float* nrow = outp + (size_t)(y + dy) * WW + xb + dx;
            const float bt = sbias[i];

            const float d0 = (c0 - nrow[0]) + bt;
            const float d1 = (c1 - nrow[1]) + bt;
            const float d2 = (c2 - nrow[2]) + bt;
            const float d3 = (c3 - nrow[3]) + bt;

            acc = fmaf(wv.x * d0, d0, acc);
            acc = fmaf(wv.y * d1, d1, acc);
            acc = fmaf(wv.z * d2, d2, acc);
            acc = fmaf(wv.w * d3, d3, acc);
        }
    }

    // Block reduction (4 warps)
    __shared__ float swarp[4];
    const float wsum = warp_reduce(acc);
    if ((tid & 31) == 0) swarp[tid >> 5] = wsum;
    __syncthreads();
    if (tid == 0) {
        g_smooth_part[b] = (double)(swarp[0] + swarp[1] + swarp[2] + swarp[3]);
    }
}

// Fidelity: sum (output - target)^2 over 512*512 elements.
// 256 blocks x 256 threads, one float4 per thread (65536 float4s exactly).
__global__ __launch_bounds__(256) void fid_kernel(
    const float* __restrict__ outp,
    const float* __restrict__ targ)
{
    const int idx = blockIdx.x * 256 + threadIdx.x;
    const float4 o = reinterpret_cast<const float4*>(outp)[idx];
    const float4 t = reinterpret_cast<const float4*>(targ)[idx];
    const float e0 = o.x - t.x;
    const float e1 = o.y - t.y;
    const float e2 = o.z - t.z;
    const float e3 = o.w - t.w;
    float acc = e0 * e0 + e1 * e1 + e2 * e2 + e3 * e3;

    __shared__ float swarp[8];
    acc = warp_reduce(acc);
    if ((threadIdx.x & 31) == 0) swarp[threadIdx.x >> 5] = acc;
    __syncthreads();
    if (threadIdx.x == 0) {
        float s = 0.0f;
#pragma unroll
        for (int i = 0; i < 8; ++i) s += swarp[i];
        g_fid_part[blockIdx.x] = (double)s;
    }
}

// Single-block final reduction over partials; writes the scalar result.
__global__ __launch_bounds__(256) void finalize_kernel(float* __restrict__ out)
{
    double s = 0.0, f = 0.0;
    for (int i = threadIdx.x; i < SMOOTH_BLOCKS; i += 256) s += g_smooth_part[i];
    for (int i = threadIdx.x; i < FID_BLOCKS; i += 256)    f += g_fid_part[i];

    __shared__ double ss[256];
    __shared__ double sf[256];
    ss[threadIdx.x] = s;
    sf[threadIdx.x] = f;
    __syncthreads();
#pragma unroll
    for (int stride = 128; stride > 0; stride >>= 1) {
        if (threadIdx.x < stride) {
            ss[threadIdx.x] += ss[threadIdx.x + stride];
            sf[threadIdx.x] += sf[threadIdx.x + stride];
        }
        __syncthreads();
    }
    if (threadIdx.x == 0) {
        // smooth = H*W*LAM * mean(w*d*d);  fidelity = mean((o-t)^2)
        const double n_smooth = (double)NTAP * (double)HO * (double)WO;
        const double smooth = (double)HH * (double)WW * 128.0 * (ss[0] / n_smooth);
        const double fid    = sf[0] / ((double)HH * (double)WW);
        out[0] = (float)(smooth + fid);
    }
}

extern "C" void kernel_launch(void* const* d_in, const int* in_sizes, int n_in,
                              void* d_out, int out_size)
{
    const float* outp = (const float*)d_in[0];   // output (H, W)
    const float* targ = (const float*)d_in[1];   // target (H, W)
    const float* wij  = (const float*)d_in[2];   // w_ij (440, 492, 492)
    const float* bias = (const float*)d_in[3];   // bias (440,)
    float* out = (float*)d_out;

    smooth_kernel<<<SMOOTH_BLOCKS, 128>>>(outp, wij, bias);
    fid_kernel<<<FID_BLOCKS, 256>>>(outp, targ);
    finalize_kernel<<<1, 256>>>(out);
}